// round 11
// baseline (speedup 1.0000x reference)
#include <cuda_runtime.h>
#include <math.h>

#define BB   16
#define NN   96
#define HH   256
#define BINC 11

// Scratch (__device__ globals: no allocation).
__device__ float g_yb [BB * NN * HH];   // y + b_bin   (base rows, 1.5 MB)
__device__ float g_yT [BB * HH * NN];   // y transposed [b][k][j] (1.5 MB)

// ---- packed f32x2 helpers (u64 carrier, "l" constraints) ------------------
typedef unsigned long long f2;
__device__ __forceinline__ f2 pk(float lo, float hi) {
    f2 r; asm("mov.b64 %0, {%1,%2};" : "=l"(r) : "f"(lo), "f"(hi)); return r;
}
__device__ __forceinline__ void upk(f2 v, float& lo, float& hi) {
    asm("mov.b64 {%0,%1}, %2;" : "=f"(lo), "=f"(hi) : "l"(v));
}
__device__ __forceinline__ f2 fma2(f2 a, f2 b, f2 c) {
    f2 d; asm("fma.rn.f32x2 %0, %1, %2, %3;" : "=l"(d) : "l"(a), "l"(b), "l"(c)); return d;
}
__device__ __forceinline__ f2 add2(f2 a, f2 b) {
    f2 d; asm("add.rn.f32x2 %0, %1, %2;" : "=l"(d) : "l"(a), "l"(b)); return d;
}

#define PR 8
#define PROJ_BLOCKS  ((BB * NN / PR) * 2)   // 384 (row-group x k-half)
#define WRITE_BLOCKS (BB * NN / 4)          // 384 (4 i-rows each)

// ---------------------------------------------------------------------------
// Kernel 1: block-specialized overlap.
//   blocks [0,384):   proj  y = x @ W_atom    (latency-bound, ~1% DRAM)
//   blocks [384,768): pair[i,j,:] = x_i + x_j (DRAM-bound streaming)
// The two families have complementary resource profiles and co-schedule.
// ---------------------------------------------------------------------------
__global__ __launch_bounds__(512) void proj_write_kernel(
    const float* __restrict__ x,
    const float* __restrict__ W,
    const float* __restrict__ b_bin,
    float* __restrict__ pair_out)
{
    const int tid = threadIdx.x;

    if (blockIdx.x < PROJ_BLOCKS) {
        // ================= proj (R10 version) =================
        __shared__ float xs[PR * HH];              // 8 KB
        __shared__ float part[3][PR * 128];        // 12 KB
        const int rg  = blockIdx.x >> 1;
        const int kh  = blockIdx.x & 1;
        const int r0  = rg * PR;                   // 8 rows, same batch
        const int kl  = tid & 127;
        const int k   = kh * 128 + kl;
        const int q   = tid >> 7;                  // h-quarter 0..3
        const int b   = r0 / NN;
        const int jl  = r0 % NN;

        for (int idx = tid; idx < PR * HH; idx += 512) xs[idx] = x[r0 * HH + idx];
        __syncthreads();

        f2 acc[PR];
#pragma unroll
        for (int r = 0; r < PR; ++r) acc[r] = 0ull;

        const ulonglong2* xs2 = (const ulonglong2*)xs;   // [r*64 + h4]
        const int h4base = q * 16;

        const float* W0 = W + (h4base * 4) * HH + k;
        float a0 = __ldg(W0 + 0 * HH), a1 = __ldg(W0 + 1 * HH);
        float a2 = __ldg(W0 + 2 * HH), a3 = __ldg(W0 + 3 * HH);
        const float* W1 = W0 + 4 * HH;
        float e0 = __ldg(W1 + 0 * HH), e1 = __ldg(W1 + 1 * HH);
        float e2 = __ldg(W1 + 2 * HH), e3 = __ldg(W1 + 3 * HH);

#pragma unroll 2
        for (int h4i = 0; h4i < 16; h4i += 2) {
            {
                f2 wa = pk(a0, a1), wbq = pk(a2, a3);
                if (h4i < 14) {
                    const float* Wn = W0 + 8 * HH;
                    a0 = __ldg(Wn + 0 * HH); a1 = __ldg(Wn + 1 * HH);
                    a2 = __ldg(Wn + 2 * HH); a3 = __ldg(Wn + 3 * HH);
                    W0 = Wn;
                }
                const int h4 = h4base + h4i;
#pragma unroll
                for (int r = 0; r < PR; ++r) {
                    ulonglong2 xv = xs2[r * 64 + h4];
                    acc[r] = fma2(xv.x, wa, acc[r]);
                    acc[r] = fma2(xv.y, wbq, acc[r]);
                }
            }
            {
                f2 wa = pk(e0, e1), wbq = pk(e2, e3);
                if (h4i < 13) {
                    const float* Wn = W1 + 8 * HH;
                    e0 = __ldg(Wn + 0 * HH); e1 = __ldg(Wn + 1 * HH);
                    e2 = __ldg(Wn + 2 * HH); e3 = __ldg(Wn + 3 * HH);
                    W1 = Wn;
                }
                const int h4 = h4base + h4i + 1;
#pragma unroll
                for (int r = 0; r < PR; ++r) {
                    ulonglong2 xv = xs2[r * 64 + h4];
                    acc[r] = fma2(xv.x, wa, acc[r]);
                    acc[r] = fma2(xv.y, wbq, acc[r]);
                }
            }
        }

        if (q > 0) {
#pragma unroll
            for (int r = 0; r < PR; ++r) {
                float lo, hi; upk(acc[r], lo, hi);
                part[q - 1][r * 128 + kl] = lo + hi;
            }
        }
        __syncthreads();
        if (q == 0) {
            const float bbk = __ldg(&b_bin[k]);
#pragma unroll
            for (int r = 0; r < PR; ++r) {
                float lo, hi; upk(acc[r], lo, hi);
                const float v = lo + hi + part[0][r * 128 + kl]
                              + part[1][r * 128 + kl] + part[2][r * 128 + kl];
                g_yb[(r0 + r) * HH + k]          = v + bbk;
                g_yT[(b * HH + k) * NN + jl + r] = v;
            }
        }
    } else {
        // ================= pair writer (att-free) =================
        const int wb = blockIdx.x - PROJ_BLOCKS;   // 0..383
        const int r0 = wb * 4;                     // 4 rows, same batch
        const int b  = r0 / NN;
        const int i0 = r0 % NN;
        const int tq = tid & 63;                   // k-quad
        const int ph = tid >> 6;                   // j-phase 0..7

        const float4* x4 = (const float4*)(x + (size_t)b * NN * HH);

#pragma unroll
        for (int ii = 0; ii < 4; ++ii) {
            const float4 xi4 = x4[(i0 + ii) * 64 + tq];
            float4* po = (float4*)(pair_out + (size_t)(r0 + ii) * NN * HH);
#pragma unroll
            for (int jj = 0; jj < NN / 8; ++jj) {
                const int j = ph + 8 * jj;
                const float4 xj = x4[j * 64 + tq];   // L1/L2-resident after ii=0
                __stcs(&po[j * 64 + tq],
                       make_float4(xi4.x + xj.x, xi4.y + xj.y,
                                   xi4.z + xj.z, xi4.w + xj.w));
            }
        }
    }
}

// ---------------------------------------------------------------------------
// Kernel 2: scores (2 j per thread) + fused context. Block = (b, 4 i), 192 thr.
// att never leaves shared. Ctx epilogue: thread owns k, shares each x[b,j,k]
// read across the 4 i's (37.7 MB L2 total).
// ---------------------------------------------------------------------------
__global__ __launch_bounds__(192, 3) void score_ctx_kernel(
    const float* __restrict__ x,
    const float* __restrict__ bin,
    const float* __restrict__ W_bin,
    const float* __restrict__ w_score,
    const float* __restrict__ b_score,
    float* __restrict__ ctx_out)
{
    __shared__ float Wb_s[BINC * HH];      // 11 KB
    __shared__ float ws_s[HH];             // 1 KB
    __shared__ float yb_s[4 * HH];         // 4 KB
    __shared__ float sbin[4 * NN * BINC];  // 16.5 KB
    __shared__ float att_s[4][NN];         // 1.5 KB

    const int blk = blockIdx.x;            // 0..383
    const int b   = blk / (NN / 4);
    const int i0  = (blk % (NN / 4)) * 4;
    const int tid = threadIdx.x;
    const int iw  = tid / 48;               // i within block
    const int jt  = tid % 48;                // j-pair index
    const int j0  = 2 * jt;

    // ---- stage operands (coalesced) ----
    for (int idx = tid; idx < BINC * HH; idx += 192) Wb_s[idx] = W_bin[idx];
    for (int idx = tid; idx < HH; idx += 192)        ws_s[idx] = w_score[idx];
    for (int idx = tid; idx < 4 * HH; idx += 192)
        yb_s[idx] = g_yb[(b * NN + i0) * HH + idx];
    {
        const float* src = bin + (size_t)(b * NN + i0) * NN * BINC;
        for (int idx = tid; idx < 4 * NN * BINC; idx += 192) sbin[idx] = src[idx];
    }
    __syncthreads();

    // ---- scores: thread owns (iw, j0, j0+1) ----
    {
        f2 bc0[BINC], bc1[BINC];
#pragma unroll
        for (int c = 0; c < BINC; ++c) {
            const float v0 = sbin[(iw * NN + j0) * BINC + c];
            const float v1 = sbin[(iw * NN + j0 + 1) * BINC + c];
            bc0[c] = pk(v0, v0);
            bc1[c] = pk(v1, v1);
        }

        const float2* yT2 = (const float2*)(g_yT + (size_t)b * HH * NN) + jt;
        const ulonglong2* wbp = (const ulonglong2*)Wb_s;     // [c*64 + k4]
        const ulonglong2* bsp = (const ulonglong2*)(yb_s + iw * HH);
        const ulonglong2* wsp = (const ulonglong2*)ws_s;

        float2 q0 = yT2[0 * 48], q1 = yT2[1 * 48], q2 = yT2[2 * 48], q3 = yT2[3 * 48];

        f2 accA = 0ull, accB = 0ull;
        for (int k4 = 0; k4 < HH / 4; ++k4) {
            ulonglong2 bs = bsp[k4];
            f2 hA01 = add2(bs.x, pk(q0.x, q1.x));
            f2 hA23 = add2(bs.y, pk(q2.x, q3.x));
            f2 hB01 = add2(bs.x, pk(q0.y, q1.y));
            f2 hB23 = add2(bs.y, pk(q2.y, q3.y));

            if (k4 < HH / 4 - 1) {
                const float2* yn = yT2 + (k4 * 4 + 4) * 48;
                q0 = yn[0 * 48]; q1 = yn[1 * 48];
                q2 = yn[2 * 48]; q3 = yn[3 * 48];
            }

#pragma unroll
            for (int c = 0; c < BINC; ++c) {
                ulonglong2 wv = wbp[c * 64 + k4];
                hA01 = fma2(bc0[c], wv.x, hA01);
                hA23 = fma2(bc0[c], wv.y, hA23);
                hB01 = fma2(bc1[c], wv.x, hB01);
                hB23 = fma2(bc1[c], wv.y, hB23);
            }

            float a0, a1, a2, a3, b0, b1, b2, b3;
            upk(hA01, a0, a1); upk(hA23, a2, a3);
            upk(hB01, b0, b1); upk(hB23, b2, b3);
            a0 = fmaxf(a0, 0.f); a1 = fmaxf(a1, 0.f); a2 = fmaxf(a2, 0.f); a3 = fmaxf(a3, 0.f);
            b0 = fmaxf(b0, 0.f); b1 = fmaxf(b1, 0.f); b2 = fmaxf(b2, 0.f); b3 = fmaxf(b3, 0.f);

            ulonglong2 wsv = wsp[k4];
            accA = fma2(pk(a0, a1), wsv.x, accA);
            accA = fma2(pk(a2, a3), wsv.y, accA);
            accB = fma2(pk(b0, b1), wsv.x, accB);
            accB = fma2(pk(b2, b3), wsv.y, accB);
        }

        float al, ah, bl, bh;
        upk(accA, al, ah); upk(accB, bl, bh);
        const float bsc = __ldg(b_score);
        att_s[iw][j0]     = 1.f / (1.f + __expf(-(al + ah + bsc)));
        att_s[iw][j0 + 1] = 1.f / (1.f + __expf(-(bl + bh + bsc)));
    }
    __syncthreads();

    // ---- fused context: thread owns k; x[b,j,k] shared across the 4 i's ----
    for (int k = tid; k < HH; k += 192) {
        const float* xp = x + (size_t)b * NN * HH + k;
        float c0 = 0.f, c1 = 0.f, c2 = 0.f, c3 = 0.f;
#pragma unroll 4
        for (int j = 0; j < NN; ++j) {
            const float xv = __ldg(xp + j * HH);
            c0 = fmaf(att_s[0][j], xv, c0);
            c1 = fmaf(att_s[1][j], xv, c1);
            c2 = fmaf(att_s[2][j], xv, c2);
            c3 = fmaf(att_s[3][j], xv, c3);
        }
        float* co = ctx_out + (size_t)(b * NN + i0) * HH + k;
        co[0 * HH] = c0; co[1 * HH] = c1; co[2 * HH] = c2; co[3 * HH] = c3;
    }
}

// ---------------------------------------------------------------------------
extern "C" void kernel_launch(void* const* d_in, const int* in_sizes, int n_in,
                              void* d_out, int out_size) {
    const float* x       = (const float*)d_in[0];
    const float* bin     = (const float*)d_in[1];
    const float* W_atom  = (const float*)d_in[2];
    const float* W_bin   = (const float*)d_in[3];
    const float* b_bin   = (const float*)d_in[4];
    const float* w_score = (const float*)d_in[5];
    const float* b_score = (const float*)d_in[6];

    float* out  = (float*)d_out;
    float* ctx  = out;                            // context: B*N*H
    float* pair = out + (size_t)BB * NN * HH;     // atom_pair: B*N*N*H

    proj_write_kernel<<<PROJ_BLOCKS + WRITE_BLOCKS, 512>>>(x, W_atom, b_bin, pair);
    score_ctx_kernel <<<BB * NN / 4, 192>>>(x, bin, W_bin, w_score, b_score, ctx);
}

// round 12
// speedup vs baseline: 1.1293x; 1.1293x over previous
#include <cuda_runtime.h>
#include <math.h>

#define BB   16
#define NN   96
#define HH   256
#define BINC 11

// Scratch (__device__ globals: no allocation).
__device__ float g_yb [BB * NN * HH];   // y + b_bin   (base rows, 1.5 MB)
__device__ float g_yT [BB * HH * NN];   // y transposed [b][k][j] (1.5 MB)
__device__ float g_att[BB * NN * NN];   // sigmoided scores (0.6 MB)

// ---- packed f32x2 helpers (u64 carrier, "l" constraints) ------------------
typedef unsigned long long f2;
__device__ __forceinline__ f2 pk(float lo, float hi) {
    f2 r; asm("mov.b64 %0, {%1,%2};" : "=l"(r) : "f"(lo), "f"(hi)); return r;
}
__device__ __forceinline__ void upk(f2 v, float& lo, float& hi) {
    asm("mov.b64 {%0,%1}, %2;" : "=f"(lo), "=f"(hi) : "l"(v));
}
__device__ __forceinline__ f2 fma2(f2 a, f2 b, f2 c) {
    f2 d; asm("fma.rn.f32x2 %0, %1, %2, %3;" : "=l"(d) : "l"(a), "l"(b), "l"(c)); return d;
}
__device__ __forceinline__ f2 add2(f2 a, f2 b) {
    f2 d; asm("add.rn.f32x2 %0, %1, %2;" : "=l"(d) : "l"(a), "l"(b)); return d;
}

// ---------------------------------------------------------------------------
// Kernel 1: y = x @ W_atom.
// Grid = 384: (row-group of 8) x (k-half of 128). Block 512 = 128 k x 4 h-q.
// Depth-2 software pipeline on W loads. g_yT written as 2x STG.128 per thread.
// ---------------------------------------------------------------------------
#define PR 8
__global__ __launch_bounds__(512) void proj_kernel(const float* __restrict__ x,
                                                   const float* __restrict__ W,
                                                   const float* __restrict__ b_bin) {
    __shared__ float xs[PR * HH];              // 8 KB
    __shared__ float part[3][PR * 128];        // 12 KB
    const int rg  = blockIdx.x >> 1;
    const int kh  = blockIdx.x & 1;
    const int r0  = rg * PR;                   // 8 rows, same batch
    const int tid = threadIdx.x;
    const int kl  = tid & 127;                 // local k 0..127
    const int k   = kh * 128 + kl;             // global k
    const int q   = tid >> 7;                  // h-quarter 0..3
    const int b   = r0 / NN;
    const int jl  = r0 % NN;

    for (int idx = tid; idx < PR * HH; idx += 512) xs[idx] = x[r0 * HH + idx];
    __syncthreads();

    f2 acc[PR];
#pragma unroll
    for (int r = 0; r < PR; ++r) acc[r] = 0ull;

    const ulonglong2* xs2 = (const ulonglong2*)xs;   // [r*64 + h4]
    const int h4base = q * 16;

    const float* W0 = W + (h4base * 4) * HH + k;
    float a0 = __ldg(W0 + 0 * HH), a1 = __ldg(W0 + 1 * HH);
    float a2 = __ldg(W0 + 2 * HH), a3 = __ldg(W0 + 3 * HH);
    const float* W1 = W0 + 4 * HH;
    float e0 = __ldg(W1 + 0 * HH), e1 = __ldg(W1 + 1 * HH);
    float e2 = __ldg(W1 + 2 * HH), e3 = __ldg(W1 + 3 * HH);

#pragma unroll 2
    for (int h4i = 0; h4i < 16; h4i += 2) {
        {
            f2 wa = pk(a0, a1), wbq = pk(a2, a3);
            if (h4i < 14) {
                const float* Wn = W0 + 8 * HH;
                a0 = __ldg(Wn + 0 * HH); a1 = __ldg(Wn + 1 * HH);
                a2 = __ldg(Wn + 2 * HH); a3 = __ldg(Wn + 3 * HH);
                W0 = Wn;
            }
            const int h4 = h4base + h4i;
#pragma unroll
            for (int r = 0; r < PR; ++r) {
                ulonglong2 xv = xs2[r * 64 + h4];
                acc[r] = fma2(xv.x, wa, acc[r]);
                acc[r] = fma2(xv.y, wbq, acc[r]);
            }
        }
        {
            f2 wa = pk(e0, e1), wbq = pk(e2, e3);
            if (h4i < 13) {
                const float* Wn = W1 + 8 * HH;
                e0 = __ldg(Wn + 0 * HH); e1 = __ldg(Wn + 1 * HH);
                e2 = __ldg(Wn + 2 * HH); e3 = __ldg(Wn + 3 * HH);
                W1 = Wn;
            }
            const int h4 = h4base + h4i + 1;
#pragma unroll
            for (int r = 0; r < PR; ++r) {
                ulonglong2 xv = xs2[r * 64 + h4];
                acc[r] = fma2(xv.x, wa, acc[r]);
                acc[r] = fma2(xv.y, wbq, acc[r]);
            }
        }
    }

    if (q > 0) {
#pragma unroll
        for (int r = 0; r < PR; ++r) {
            float lo, hi; upk(acc[r], lo, hi);
            part[q - 1][r * 128 + kl] = lo + hi;
        }
    }
    __syncthreads();
    if (q == 0) {
        const float bbk = __ldg(&b_bin[k]);
        float vals[PR];
#pragma unroll
        for (int r = 0; r < PR; ++r) {
            float lo, hi; upk(acc[r], lo, hi);
            vals[r] = lo + hi + part[0][r * 128 + kl]
                    + part[1][r * 128 + kl] + part[2][r * 128 + kl];
            g_yb[(r0 + r) * HH + k] = vals[r] + bbk;   // coalesced across lanes
        }
        // g_yT: the 8 r-values are CONSECUTIVE at (b*HH+k)*NN + jl -> 2x STG.128
        float4* yt4 = (float4*)(g_yT + ((size_t)b * HH + k) * NN + jl);
        yt4[0] = make_float4(vals[0], vals[1], vals[2], vals[3]);
        yt4[1] = make_float4(vals[4], vals[5], vals[6], vals[7]);
    }
}

// ---------------------------------------------------------------------------
// Kernel 2: scores -> g_att. Block = (b, 4 i), 192 threads, 4 blocks/SM.
// Thread = (iw 0..3, jt 0..47) owns TWO adjacent j; W_bin LDS amortized over
// both; yT read as float2. No cross-lane ops.
// ---------------------------------------------------------------------------
__global__ __launch_bounds__(192, 4) void score_kernel(
    const float* __restrict__ bin,
    const float* __restrict__ W_bin,
    const float* __restrict__ w_score,
    const float* __restrict__ b_score)
{
    __shared__ float Wb_s[BINC * HH];      // 11 KB
    __shared__ float ws_s[HH];             // 1 KB
    __shared__ float yb_s[4 * HH];         // 4 KB
    __shared__ float sbin[4 * NN * BINC];  // 16.5 KB

    const int blk = blockIdx.x;            // 0..383
    const int b   = blk / (NN / 4);
    const int i0  = (blk % (NN / 4)) * 4;
    const int tid = threadIdx.x;
    const int iw  = tid / 48;               // i within block
    const int jt  = tid % 48;                // j-pair index
    const int j0  = 2 * jt;

    // ---- stage operands (coalesced) ----
    for (int idx = tid; idx < BINC * HH; idx += 192) Wb_s[idx] = W_bin[idx];
    for (int idx = tid; idx < HH; idx += 192)        ws_s[idx] = w_score[idx];
    for (int idx = tid; idx < 4 * HH; idx += 192)
        yb_s[idx] = g_yb[(b * NN + i0) * HH + idx];
    {
        const float* src = bin + (size_t)(b * NN + i0) * NN * BINC;
        for (int idx = tid; idx < 4 * NN * BINC; idx += 192) sbin[idx] = src[idx];
    }
    __syncthreads();

    f2 bc0[BINC], bc1[BINC];
#pragma unroll
    for (int c = 0; c < BINC; ++c) {
        const float v0 = sbin[(iw * NN + j0) * BINC + c];
        const float v1 = sbin[(iw * NN + j0 + 1) * BINC + c];
        bc0[c] = pk(v0, v0);
        bc1[c] = pk(v1, v1);
    }

    const float2* yT2 = (const float2*)(g_yT + (size_t)b * HH * NN) + jt; // [k]: +k*48
    const ulonglong2* wbp = (const ulonglong2*)Wb_s;     // [c*64 + k4]
    const ulonglong2* bsp = (const ulonglong2*)(yb_s + iw * HH);
    const ulonglong2* wsp = (const ulonglong2*)ws_s;

    float2 q0 = yT2[0 * 48], q1 = yT2[1 * 48], q2 = yT2[2 * 48], q3 = yT2[3 * 48];

    f2 accA = 0ull, accB = 0ull;
    for (int k4 = 0; k4 < HH / 4; ++k4) {
        ulonglong2 bs = bsp[k4];
        f2 hA01 = add2(bs.x, pk(q0.x, q1.x));
        f2 hA23 = add2(bs.y, pk(q2.x, q3.x));
        f2 hB01 = add2(bs.x, pk(q0.y, q1.y));
        f2 hB23 = add2(bs.y, pk(q2.y, q3.y));

        if (k4 < HH / 4 - 1) {
            const float2* yn = yT2 + (k4 * 4 + 4) * 48;
            q0 = yn[0 * 48]; q1 = yn[1 * 48];
            q2 = yn[2 * 48]; q3 = yn[3 * 48];
        }

#pragma unroll
        for (int c = 0; c < BINC; ++c) {
            ulonglong2 wv = wbp[c * 64 + k4];
            hA01 = fma2(bc0[c], wv.x, hA01);
            hA23 = fma2(bc0[c], wv.y, hA23);
            hB01 = fma2(bc1[c], wv.x, hB01);
            hB23 = fma2(bc1[c], wv.y, hB23);
        }

        float a0, a1, a2, a3, b0, b1, b2, b3;
        upk(hA01, a0, a1); upk(hA23, a2, a3);
        upk(hB01, b0, b1); upk(hB23, b2, b3);
        a0 = fmaxf(a0, 0.f); a1 = fmaxf(a1, 0.f); a2 = fmaxf(a2, 0.f); a3 = fmaxf(a3, 0.f);
        b0 = fmaxf(b0, 0.f); b1 = fmaxf(b1, 0.f); b2 = fmaxf(b2, 0.f); b3 = fmaxf(b3, 0.f);

        ulonglong2 wsv = wsp[k4];
        accA = fma2(pk(a0, a1), wsv.x, accA);
        accA = fma2(pk(a2, a3), wsv.y, accA);
        accB = fma2(pk(b0, b1), wsv.x, accB);
        accB = fma2(pk(b2, b3), wsv.y, accB);
    }

    float al, ah, bl, bh;
    upk(accA, al, ah); upk(accB, bl, bh);
    const float bsc = __ldg(b_score);
    const float s0 = al + ah + bsc;
    const float s1 = bl + bh + bsc;
    const float at0 = 1.f / (1.f + __expf(-s0));
    const float at1 = 1.f / (1.f + __expf(-s1));
    float2* ao = (float2*)(g_att + (size_t)(b * NN + i0 + iw) * NN);
    ao[jt] = make_float2(at0, at1);
}

// ---------------------------------------------------------------------------
// Kernel 3: streaming writer + fused context.
// Block = (b,i). pair[i,j,k] = x_i[k]+x_j[k] via float4 __stcs.
// ---------------------------------------------------------------------------
__global__ __launch_bounds__(256) void writer_kernel(
    const float* __restrict__ x,
    float* __restrict__ ctx_out,
    float* __restrict__ pair_out)
{
    const int blk = blockIdx.x;            // b*NN + i
    const int b   = blk / NN;
    const int tid = threadIdx.x;
    const int tq  = tid & 63;              // k-quad 0..63
    const int ph  = tid >> 6;              // j-phase 0..3

    __shared__ float att_sh[NN];
    __shared__ float cpart[4][HH];

    const float4* x4 = (const float4*)(x + (size_t)b * NN * HH);   // [j*64 + q]
    const float4 xi4 = x4[(blk % NN) * 64 + tq];
    if (tid < NN) att_sh[tid] = g_att[(size_t)blk * NN + tid];
    __syncthreads();

    float4* po = (float4*)(pair_out + (size_t)blk * NN * HH);
    float c0 = 0.f, c1 = 0.f, c2 = 0.f, c3 = 0.f;
#pragma unroll 4
    for (int jj = 0; jj < NN / 4; ++jj) {
        const int j = ph + 4 * jj;
        const float4 xj = x4[j * 64 + tq];
        const float  a  = att_sh[j];
        __stcs(&po[j * 64 + tq], make_float4(xi4.x + xj.x, xi4.y + xj.y,
                                             xi4.z + xj.z, xi4.w + xj.w));
        c0 = fmaf(a, xj.x, c0); c1 = fmaf(a, xj.y, c1);
        c2 = fmaf(a, xj.z, c2); c3 = fmaf(a, xj.w, c3);
    }
    ((float4*)cpart[ph])[tq] = make_float4(c0, c1, c2, c3);
    __syncthreads();

    const int k = tid;
    ctx_out[(size_t)blk * HH + k] =
        cpart[0][k] + cpart[1][k] + cpart[2][k] + cpart[3][k];
}

// ---------------------------------------------------------------------------
extern "C" void kernel_launch(void* const* d_in, const int* in_sizes, int n_in,
                              void* d_out, int out_size) {
    const float* x       = (const float*)d_in[0];
    const float* bin     = (const float*)d_in[1];
    const float* W_atom  = (const float*)d_in[2];
    const float* W_bin   = (const float*)d_in[3];
    const float* b_bin   = (const float*)d_in[4];
    const float* w_score = (const float*)d_in[5];
    const float* b_score = (const float*)d_in[6];

    float* out  = (float*)d_out;
    float* ctx  = out;                            // context: B*N*H
    float* pair = out + (size_t)BB * NN * HH;     // atom_pair: B*N*N*H

    proj_kernel  <<<(BB * NN / PR) * 2, 512>>>(x, W_atom, b_bin);
    score_kernel <<<BB * NN / 4, 192>>>(bin, W_bin, w_score, b_score);
    writer_kernel<<<BB * NN, 256>>>(x, ctx, pair);
}